// round 17
// baseline (speedup 1.0000x reference)
#include <cuda_runtime.h>
#include <cuda_bf16.h>
#include <math.h>

#define B 8
#define D 256
#define T 2048
#define KNN 10
#define BETA 0.2f
#define THR 0.7f
#define NBLK 128                 // gate grid: (T/128) x B = 16 x 8

// ---------------- scratch (device globals; no allocations allowed) ----------
__device__ float g_invn[B * T];
__device__ __nv_bfloat16 g_xnb[B * T * D];     // fallback only
__device__ __nv_bfloat16 g_simb[B * T * T];    // fallback only
__device__ float g_rho[B * T];
__device__ float g_s[B * T];
__device__ int   g_ord[B * T];
__device__ int   g_rank[B * T];
__device__ unsigned g_segmin[B * 32 * (T / 2)];
__device__ int   g_cstart[B * T];
__device__ int   g_clen[B * T];
__device__ int   g_done;                       // last-block ticket (reset each run)
// 0 = all-singleton fast path. Statically zero; monotonic: set only when the
// gate trips, and for such an input it trips identically on every replay.
__device__ int   g_flag;

// ---------------- fallback helpers (run by ONE block, 512 threads) -----------
__device__ __forceinline__ void bitonic_sort_shared(float* key, int* ord) {
    for (int k = 2; k <= T; k <<= 1) {
        for (int j = k >> 1; j > 0; j >>= 1) {
            for (int i = threadIdx.x; i < T; i += 512) {
                int l = i ^ j;
                if (l > i) {
                    bool up = ((i & k) == 0);
                    float ki = key[i], kl = key[l];
                    int oi = ord[i], ol = ord[l];
                    bool iAfter = (ki > kl) || (ki == kl && oi > ol);
                    if (iAfter == up) {
                        key[i] = kl; key[l] = ki;
                        ord[i] = ol; ord[l] = oi;
                    }
                }
            }
            __syncthreads();
        }
    }
}

__device__ __forceinline__ void ins11(float v, float* a) {
#pragma unroll
    for (int k = 0; k < 11; k++) {
        if (v > a[k]) { float tmp = a[k]; a[k] = v; v = tmp; }
    }
}

// Full reference pipeline for one batch b. Correctness-only path: never runs
// for gate-clean inputs; one block / 512 threads is sufficient and exact.
__device__ void fallback_batch(int b, const float* __restrict__ x,
                               float* __restrict__ out, float* lens_out,
                               char* smem) {
    int tid = threadIdx.x;
    int wid = tid >> 5, lane = tid & 31;
    const unsigned full = 0xffffffffu;

    // ---- S1: transpose + normalize -> xnb[b] ----
    for (int idx = tid; idx < T * D; idx += 512) {
        int t = idx >> 8, d = idx & 255;               // D = 256
        g_xnb[((size_t)b * T + t) * D + d] =
            __float2bfloat16(x[(size_t)b * D * T + (size_t)d * T + t] * g_invn[b * T + t]);
    }
    __syncthreads();

    // ---- S2: sim = (xn @ xn^T + 1)/2, bf16 store ----
    {
        const __nv_bfloat16* Ab = g_xnb + (size_t)b * T * D;
        __nv_bfloat16* C = g_simb + (size_t)b * T * T;
        for (int ij = tid; ij < T * T; ij += 512) {
            int i = ij >> 11, j = ij & (T - 1);
            const __nv_bfloat162* ar = (const __nv_bfloat162*)(Ab + (size_t)i * D);
            const __nv_bfloat162* br = (const __nv_bfloat162*)(Ab + (size_t)j * D);
            float acc = 0.f;
#pragma unroll 8
            for (int k = 0; k < D / 2; k++) {
                float2 fa = __bfloat1622float2(ar[k]);
                float2 fb = __bfloat1622float2(br[k]);
                acc += fa.x * fb.x + fa.y * fb.y;
            }
            C[(size_t)i * T + j] = __float2bfloat16((acc + 1.f) * 0.5f);
        }
    }
    __syncthreads();

    // ---- S3: rho (one warp per row, rows strided by 16 warps) ----
    for (int i = wid; i < T; i += 16) {
        const uint4* r16 = (const uint4*)(g_simb + ((size_t)b * T + i) * T);
        float a[11];
#pragma unroll
        for (int k = 0; k < 11; k++) a[k] = -1e30f;
#pragma unroll
        for (int jt = 0; jt < 8; jt++) {
            uint4 v0 = r16[lane + jt * 32];
            __nv_bfloat162 p[4];
            p[0] = *(__nv_bfloat162*)&v0.x; p[1] = *(__nv_bfloat162*)&v0.y;
            p[2] = *(__nv_bfloat162*)&v0.z; p[3] = *(__nv_bfloat162*)&v0.w;
            __nv_bfloat162 m = __hmax2(__hmax2(p[0], p[1]), __hmax2(p[2], p[3]));
            float fm = fmaxf(__low2float(m), __high2float(m));
            if (fm > a[10]) {
#pragma unroll
                for (int q = 0; q < 4; q++) {
                    float lo = __low2float(p[q]), hi = __high2float(p[q]);
                    if (lo > a[10]) ins11(lo, a);
                    if (hi > a[10]) ins11(hi, a);
                }
            }
        }
        float sum = 0.f;
#pragma unroll
        for (int r = 0; r < 11; r++) {
            float h = a[0], m = h;
#pragma unroll
            for (int o = 16; o > 0; o >>= 1)
                m = fmaxf(m, __shfl_xor_sync(full, m, o));
            unsigned msk = __ballot_sync(full, h == m);
            int winner = __ffs(msk) - 1;
            if (lane == winner) {
#pragma unroll
                for (int k = 0; k < 10; k++) a[k] = a[k + 1];
                a[10] = -1e30f;
            }
            if (r > 0) sum += m;            // ranks 1..10 (rank 0 = self)
        }
        if (lane == 0) g_rho[b * T + i] = expf(-sum * (1.0f / KNN));
    }
    __syncthreads();

    // ---- S4: sort rows by rho desc ----
    {
        float* key = (float*)smem;
        int* ord = (int*)(key + T);
        for (int t = tid; t < T; t += 512) { key[t] = -g_rho[b * T + t]; ord[t] = t; }
        __syncthreads();
        bitonic_sort_shared(key, ord);
        for (int k = tid; k < T; k += 512) {
            int t = ord[k];
            g_ord[b * T + k] = t;
            g_rank[b * T + t] = k;
        }
    }
    __syncthreads();

    // ---- S5: segment mins over rho-ordered rows ----
    {
        const __nv_bfloat16* S = g_simb + (size_t)b * T * T;
        for (int item = tid; item < 32 * (T / 2); item += 512) {
            int seg = item >> 10, cp = item & (T / 2 - 1);
            const int* ordp = g_ord + b * T + seg * 64;
            __nv_bfloat162 run = __floats2bfloat162_rn(1e30f, 1e30f);
            for (int k = 0; k < 64; k++) {
                unsigned u = *(const unsigned*)(S + (size_t)ordp[k] * T + cp * 2);
                run = __hmin2(run, *(__nv_bfloat162*)&u);
            }
            g_segmin[((size_t)b * 32 + seg) * (T / 2) + cp] = *(unsigned*)&run;
        }
    }
    __syncthreads();

    // ---- S6: delta fix-up + s = rho*delta ----
    {
        const __nv_bfloat16* S = g_simb + (size_t)b * T * T;
        for (int i = tid; i < T; i += 512) {
            float rho_i = g_rho[b * T + i];
            int r = g_rank[b * T + i];
            int seg_i = r >> 6;
            float mn = 1e30f;
            const unsigned* segm = g_segmin + (size_t)b * 32 * (T / 2) + (i >> 1);
            for (int s = 0; s < seg_i; s++) {
                unsigned u = segm[(size_t)s * (T / 2)];
                __nv_bfloat162 p = *(__nv_bfloat162*)&u;
                float v = (i & 1) ? __high2float(p) : __low2float(p);
                mn = fminf(mn, v);
            }
            const int* ordp = g_ord + b * T + (seg_i << 6);
            int nown = r - (seg_i << 6);
            for (int k = 0; k < nown; k++) {
                int row = ordp[k];
                if (g_rho[b * T + row] > rho_i)    // strict (matches reference)
                    mn = fminf(mn, __bfloat162float(S[(size_t)row * T + i]));
            }
            float delta = (mn < 1e29f) ? mn
                                       : __bfloat162float(S[(size_t)i * T + i]);
            g_s[b * T + i] = rho_i * delta;
        }
    }
    __syncthreads();

    // ---- S7: clustering (chunked greedy, warp 0 serial core) ----
    {
        float* s_sh = (float*)smem;
        float* key  = s_sh + T;
        int* ordA = (int*)(key + T);
        int* lenA = ordA + T;
        int* staA = lenA + T;
        unsigned* thr_sh = (unsigned*)(staA + T);
        unsigned* asgw = thr_sh + T;
        int* sh_ncl = (int*)(asgw + 66);

        for (int t = tid; t < T; t += 512) s_sh[t] = g_s[b * T + t];
        for (int t = tid; t < 66; t += 512) asgw[t] = 0u;
        __syncthreads();

        for (int t = tid; t < T; t += 512) {
            unsigned m = 0;
            const __nv_bfloat16* row = g_simb + ((size_t)b * T + t) * T;
#pragma unroll
            for (int k = 0; k < 9; k++) {
                if (k == 4) continue;
                int j = t - 4 + k;
                if (j >= 0 && j < T &&
                    (__bfloat162float(row[j]) - BETA * s_sh[j] > THR)) m |= 1u << k;
            }
            thr_sh[t] = m;
        }

        for (int t = tid; t < T; t += 512) { key[t] = -s_sh[t]; ordA[t] = t; }
        __syncthreads();
        bitonic_sort_shared(key, ordA);

        if (tid < 32) {
            int lane2 = tid;
            int cid_base = 0;
            for (int p = 0; p < T; p += 32) {
                int seed = ordA[p + lane2];
                unsigned thrm = thr_sh[seed];
                int bitpos = seed + 28;
                unsigned w0 = asgw[bitpos >> 5];
                unsigned w1 = asgw[(bitpos >> 5) + 1];
                unsigned A = (unsigned)(((((unsigned long long)w1 << 32) | w0)
                                         >> (bitpos & 31))) & 0x1FFu;
                bool pre = (A >> 4) & 1u;
                bool isfast = !pre && (thrm == 0u);
                bool isslow = !pre && (thrm != 0u);
                unsigned slowm = __ballot_sync(full, isslow);
                bool committed = false;
                int st = seed, sz = 1;

                if (slowm == 0u) {
                    committed = isfast;
                } else {
                    unsigned rem = slowm;
                    while (rem) {
                        int i = __ffs(rem) - 1; rem &= rem - 1;
                        int wb_i = __shfl_sync(full, seed, i) - 4;
                        unsigned contrib = 0u;
                        int lo = -1, hi = -2;
                        if (committed) {
                            lo = max(st, wb_i); hi = min(st + sz - 1, wb_i + 8);
                        } else if (isfast && lane2 < i) {
                            lo = max(seed, wb_i); hi = min(seed, wb_i + 8);
                        }
                        if (lo <= hi) contrib = ((1u << (hi - lo + 1)) - 1u) << (lo - wb_i);
                        unsigned add = __reduce_or_sync(full, contrib);
                        if (lane2 == i) {
                            A |= add;
                            if (!((A >> 4) & 1u)) {
                                unsigned avail = thrm & ~A;
                                unsigned f4 = (avail >> 5) & 0xFu;
                                int f = min(__ffs(~f4) - 1, 3);
                                int size = 1 + f;
                                unsigned b4 = __brev(avail & 0xFu) >> 28;
                                int bb = min(__ffs(~b4) - 1, 4 - size);
                                st = seed - bb;
                                sz = size + bb;
                                committed = true;
                            }
                        }
                    }
                    unsigned cm = slowm;
                    bool covered = false;
                    while (cm) {
                        int j = __ffs(cm) - 1; cm &= cm - 1;
                        int stj = __shfl_sync(full, st, j);
                        int szj = __shfl_sync(full, sz, j);
                        int cmj = __shfl_sync(full, (int)committed, j);
                        if (isfast && j < lane2 && cmj && seed >= stj && seed < stj + szj)
                            covered = true;
                    }
                    if (isfast && !covered) committed = true;
                }

                unsigned cmask = __ballot_sync(full, committed);
                if (committed) {
                    int cid = cid_base + __popc(cmask & ((1u << lane2) - 1u));
                    lenA[cid] = sz;
                    staA[cid] = st;
                    int bp = st + 32;
                    unsigned long long m64 = ((1ull << sz) - 1ull) << (bp & 31);
                    atomicOr(&asgw[bp >> 5], (unsigned)m64);
                    unsigned hiw = (unsigned)(m64 >> 32);
                    if (hiw) atomicOr(&asgw[(bp >> 5) + 1], hiw);
                }
                cid_base += __popc(cmask);
                __syncwarp(full);
            }
            if (tid == 0) *sh_ncl = cid_base;
        }
        __syncthreads();

        int ncl = *sh_ncl;
        for (int c = tid; c < T; c += 512) {
            if (c >= ncl) { lenA[c] = 0; staA[c] = T; }
            key[c] = (float)(staA[c] * 4096 + c);   // stable by start (< 2^24)
            ordA[c] = c;
        }
        __syncthreads();
        bitonic_sort_shared(key, ordA);

        for (int r = tid; r < T; r += 512) {
            int c = ordA[r];
            g_clen[b * T + r] = lenA[c];
            g_cstart[b * T + r] = staA[c];
        }
    }
    __syncthreads();

    // ---- S8: mean-pool (overwrites the gate's fast-path copy) ----
    for (int idx = tid; idx < D * T; idx += 512) {
        int d = idx >> 11, r = idx & (T - 1);
        int len = g_clen[b * T + r];
        int st = g_cstart[b * T + r];
        float acc = 0.f;
        for (int k = 0; k < len; k++) acc += x[((size_t)b * D + d) * T + st + k];
        out[(size_t)b * D * T + (size_t)d * T + r] = len ? acc / (float)len : 0.f;
        if (lens_out && d == 0) lens_out[b * T + r] = (float)len;
    }
    __syncthreads();
}

// ---------------- fused kernel: gate + fast-path copy + last-block fallback --
// Growth needs sim - BETA*s > THR with s >= 0 (rho>0, delta in [0,1]), hence
// sim > THR on the +/-4 band. Gate conservatively at sim > 0.68 (dot > 0.36).
// Writes out = x and lens = 1 unconditionally (exact on the fast path).
// The LAST block (threadfence + ticket) re-checks g_flag and, if set, runs the
// whole reference pipeline itself — correctness-only, never taken when clean.
__global__ void __launch_bounds__(512) fused_kernel(const float* __restrict__ x,
                                                    float* __restrict__ out,
                                                    float* lens_out) {
    const unsigned full = 0xffffffffu;
    int b = blockIdx.y, t0 = blockIdx.x * 128;
    int tid = threadIdx.x;
    int w = tid >> 5, lane = tid & 31;
    const float* xb = x + (size_t)b * D * T;
    float* ob = out + (size_t)b * D * T;

    float dot[4][4];                 // [i][off-1], i = t position within float4
    float nrm[4] = {0.f, 0.f, 0.f, 0.f};
    float hnrm[4] = {0.f, 0.f, 0.f, 0.f};   // lane 31 only: halo norms
#pragma unroll
    for (int i = 0; i < 4; i++)
#pragma unroll
        for (int o = 0; o < 4; o++) dot[i][o] = 0.f;

    bool has_halo = (t0 + 128 < T);
    for (int d = w; d < D; d += 16) {
        const float* rowp = xb + (size_t)d * T + t0;
        float4 v = *(const float4*)(rowp + 4 * lane);
        *(float4*)(ob + (size_t)d * T + t0 + 4 * lane) = v;   // out = x copy
        float4 h = make_float4(0.f, 0.f, 0.f, 0.f);
        if (lane == 31 && has_halo) h = *(const float4*)(rowp + 128);
        float4 n;
        n.x = __shfl_down_sync(full, v.x, 1);
        n.y = __shfl_down_sync(full, v.y, 1);
        n.z = __shfl_down_sync(full, v.z, 1);
        n.w = __shfl_down_sync(full, v.w, 1);
        if (lane == 31) n = h;
        float s[8] = {v.x, v.y, v.z, v.w, n.x, n.y, n.z, n.w};
#pragma unroll
        for (int i = 0; i < 4; i++) {
            nrm[i] += s[i] * s[i];
#pragma unroll
            for (int off = 1; off <= 4; off++)
                dot[i][off - 1] += s[i] * s[i + off];
        }
        if (lane == 31) {
            hnrm[0] += n.x * n.x; hnrm[1] += n.y * n.y;
            hnrm[2] += n.z * n.z; hnrm[3] += n.w * n.w;
        }
    }

    // cross-warp (d-split) reduction
    __shared__ float red[16][5][128];    // [warp][{norm,dot1..4}][t_local]
    __shared__ float redh[16][4];
    __shared__ float inv_sh[128];
    __shared__ float invh_sh[4];
    __shared__ int sh_last;
#pragma unroll
    for (int i = 0; i < 4; i++) {
        red[w][0][4 * lane + i] = nrm[i];
#pragma unroll
        for (int o = 0; o < 4; o++) red[w][1 + o][4 * lane + i] = dot[i][o];
    }
    if (lane == 31) {
#pragma unroll
        for (int j = 0; j < 4; j++) redh[w][j] = hnrm[j];
    }
    __syncthreads();

    for (int e = tid; e < 640; e += 512) {
        int c = e >> 7, t = e & 127;
        float s = 0.f;
#pragma unroll
        for (int ww = 0; ww < 16; ww++) s += red[ww][c][t];
        red[0][c][t] = s;        // each (c,t) touched by exactly one thread
    }
    if (tid < 4) {
        float s = 0.f;
#pragma unroll
        for (int ww = 0; ww < 16; ww++) s += redh[ww][tid];
        invh_sh[tid] = 1.f / fmaxf(sqrtf(s), 1e-12f);
    }
    __syncthreads();

    if (tid < 128) {
        int t = t0 + tid;
        float invn = 1.f / fmaxf(sqrtf(red[0][0][tid]), 1e-12f);
        g_invn[b * T + t] = invn;              // fallback needs this
        if (lens_out) lens_out[b * T + t] = 1.0f;   // fast-path lens
        inv_sh[tid] = invn;
    }
    __syncthreads();

    if (tid < 128) {
        int t = t0 + tid;
        float invn = inv_sh[tid];
        float mx = -1.f;
#pragma unroll
        for (int off = 1; off <= 4; off++) {
            if (t + off < T) {
                float invo = (tid + off < 128) ? inv_sh[tid + off]
                                               : invh_sh[tid + off - 128];
                mx = fmaxf(mx, red[0][off][tid] * invn * invo);
            }
        }
        if (mx > 0.36f) atomicOr(&g_flag, 1);   // sim=(dot+1)/2 > 0.68
    }

    // ---- last-block ticket: fence, count, and (if flagged) run fallback ----
    __threadfence();
    __syncthreads();
    if (tid == 0) sh_last = (atomicAdd(&g_done, 1) == NBLK - 1);
    __syncthreads();
    if (!sh_last) return;

    if (tid == 0) g_done = 0;        // reset for the next (graph) replay
    __threadfence();
    if (g_flag != 0) {
        extern __shared__ char fb_smem[];
        for (int bb = 0; bb < B; bb++)
            fallback_batch(bb, x, out, lens_out, fb_smem);
    }
}

// ---------------- launch ------------------------------------------------------
extern "C" void kernel_launch(void* const* d_in, const int* in_sizes, int n_in,
                              void* d_out, int out_size) {
    const float* x = (const float*)d_in[0];
    float* out = (float*)d_out;
    float* lens_out = (out_size >= (int)(B * D * T + B * T)) ? out + (size_t)B * D * T
                                                             : nullptr;

    const int FB_SMEM = (6 * T + 67) * 4;   // 49420 B dynamic arena (fallback)
    cudaFuncSetAttribute(fused_kernel,
                         cudaFuncAttributeMaxDynamicSharedMemorySize, FB_SMEM);

    fused_kernel<<<dim3(T / 128, B), 512, FB_SMEM>>>(x, out, lens_out);
}